// round 1
// baseline (speedup 1.0000x reference)
#include <cuda_runtime.h>

// Problem dims (fixed by dataset): image [B=4, C=1, D=128, H=256, W=256] fp32
// Output [B, 2, D, H, W]: ch0 = image copy, ch1 = sqrt(Gx^2+Gy^2+Gz^2 + 1e-8)
#define DIM_D 128
#define DIM_H 256
#define DIM_W 256
#define DCHUNK 32

__device__ __forceinline__ float4 f4zero() { return make_float4(0.f, 0.f, 0.f, 0.f); }

// Compute per-plane separable partials for this thread's 4 output columns:
//   A = s_h * s_w (x)   (for Gz = d_d(A))
//   B = s_h * d_w (x)   (for Gx = s_d(B))
//   C = d_h * s_w (x)   (for Gy = s_d(C))
// cen = raw image value at (p, h, w0..w0+3) for the copy channel.
__device__ __forceinline__ void load_plane(
    const float* __restrict__ base, int p, int h, int w0,
    float4& A, float4& B, float4& C, float4& cen)
{
    A = f4zero(); B = f4zero(); C = f4zero(); cen = f4zero();
    if (p < 0 || p >= DIM_D) return;

    const float* pl = base + (size_t)p * (DIM_H * DIM_W);

    float4 u[3], v[3];
#pragma unroll
    for (int r = 0; r < 3; r++) {
        int hh = h - 1 + r;
        float4 c = f4zero();
        float xl = 0.f, xr = 0.f;
        if (hh >= 0 && hh < DIM_H) {
            const float* row = pl + (size_t)hh * DIM_W + w0;
            c = __ldg(reinterpret_cast<const float4*>(row));
            if (w0 > 0)            xl = __ldg(row - 1);
            if (w0 + 4 < DIM_W)    xr = __ldg(row + 4);
        }
        if (r == 1) cen = c;
        // smooth along w: [1,2,1]
        u[r].x = xl  + 2.f * c.x + c.y;
        u[r].y = c.x + 2.f * c.y + c.z;
        u[r].z = c.y + 2.f * c.z + c.w;
        u[r].w = c.z + 2.f * c.w + xr;
        // derivative along w: [-1,0,1]  (x[w+1]-x[w-1])
        v[r].x = c.y - xl;
        v[r].y = c.z - c.x;
        v[r].z = c.w - c.y;
        v[r].w = xr  - c.z;
    }

    // combine rows: smooth_h on u -> A, smooth_h on v -> B, deriv_h on u -> C
    A.x = u[0].x + 2.f * u[1].x + u[2].x;
    A.y = u[0].y + 2.f * u[1].y + u[2].y;
    A.z = u[0].z + 2.f * u[1].z + u[2].z;
    A.w = u[0].w + 2.f * u[1].w + u[2].w;

    B.x = v[0].x + 2.f * v[1].x + v[2].x;
    B.y = v[0].y + 2.f * v[1].y + v[2].y;
    B.z = v[0].z + 2.f * v[1].z + v[2].z;
    B.w = v[0].w + 2.f * v[1].w + v[2].w;

    C.x = u[2].x - u[0].x;
    C.y = u[2].y - u[0].y;
    C.z = u[2].z - u[0].z;
    C.w = u[2].w - u[0].w;
}

__global__ void __launch_bounds__(256)
sobel_edge_kernel(const float* __restrict__ img, float* __restrict__ out)
{
    const int w0 = threadIdx.x * 4;                       // 64 threads cover W=256
    const int h  = blockIdx.y * blockDim.y + threadIdx.y; // 4 rows per block
    const int d0 = blockIdx.x * DCHUNK;
    const int b  = blockIdx.z;

    const float* base = img + (size_t)b * (DIM_D * DIM_H * DIM_W);
    float* out0 = out + (size_t)b * 2 * (DIM_D * DIM_H * DIM_W);
    float* out1 = out0 + (size_t)(DIM_D * DIM_H * DIM_W);

    float4 A0, A1, A2, B0, B1, B2, C0, C1, C2, cen0, cen1, dummy;

    load_plane(base, d0 - 1, h, w0, A0, B0, C0, dummy);
    load_plane(base, d0,     h, w0, A1, B1, C1, cen0);

#pragma unroll 2
    for (int dd = 0; dd < DCHUNK; dd++) {
        const int d = d0 + dd;
        load_plane(base, d + 1, h, w0, A2, B2, C2, cen1);

        float4 gx, gy, gz, m;
        // Gx = s_d(B), Gy = s_d(C), Gz = d_d(A)
        gx.x = B0.x + 2.f * B1.x + B2.x;
        gx.y = B0.y + 2.f * B1.y + B2.y;
        gx.z = B0.z + 2.f * B1.z + B2.z;
        gx.w = B0.w + 2.f * B1.w + B2.w;

        gy.x = C0.x + 2.f * C1.x + C2.x;
        gy.y = C0.y + 2.f * C1.y + C2.y;
        gy.z = C0.z + 2.f * C1.z + C2.z;
        gy.w = C0.w + 2.f * C1.w + C2.w;

        gz.x = A2.x - A0.x;
        gz.y = A2.y - A0.y;
        gz.z = A2.z - A0.z;
        gz.w = A2.w - A0.w;

        m.x = sqrtf(gx.x * gx.x + gy.x * gy.x + gz.x * gz.x + 1e-8f);
        m.y = sqrtf(gx.y * gx.y + gy.y * gy.y + gz.y * gz.y + 1e-8f);
        m.z = sqrtf(gx.z * gx.z + gy.z * gy.z + gz.z * gz.z + 1e-8f);
        m.w = sqrtf(gx.w * gx.w + gy.w * gy.w + gz.w * gz.w + 1e-8f);

        const size_t off = ((size_t)d * DIM_H + h) * DIM_W + w0;
        *reinterpret_cast<float4*>(out0 + off) = cen0;  // copy channel
        *reinterpret_cast<float4*>(out1 + off) = m;     // magnitude channel

        A0 = A1; A1 = A2;
        B0 = B1; B1 = B2;
        C0 = C1; C1 = C2;
        cen0 = cen1;
    }
}

extern "C" void kernel_launch(void* const* d_in, const int* in_sizes, int n_in,
                              void* d_out, int out_size)
{
    const float* img = (const float*)d_in[0];
    float* out = (float*)d_out;

    dim3 block(64, 4, 1);                       // 256 threads: 64*4 w-columns x 4 h-rows
    dim3 grid(DIM_D / DCHUNK, DIM_H / 4, 4);    // 4 d-chunks x 64 h-blocks x B=4

    sobel_edge_kernel<<<grid, block>>>(img, out);
}